// round 1
// baseline (speedup 1.0000x reference)
#include <cuda_runtime.h>
#include <cstdint>
#include <cstddef>

#define BB 8
#define NN 16384
#define CC 64
#define SS 2048
#define KK 32

// Scratch (device globals: no allocation allowed)
__device__ float g_feat1[(size_t)BB * NN * 64];   // features @ W1[3:67,:]
__device__ int   g_knn[(size_t)BB * SS * KK];     // top-32 neighbor indices

// ---------------------------------------------------------------------------
// Stage 1: farthest point sampling. One block per batch. Must match the
// reference arithmetic bit-for-bit: (x-c)^2 terms with separate rounding,
// left-to-right sum, argmax with lowest-index tie-break.
// ---------------------------------------------------------------------------
__global__ __launch_bounds__(1024, 1) void fps_kernel(const float* __restrict__ xyz,
                                                      float* __restrict__ newxyz)
{
    const int b = blockIdx.x;
    extern __shared__ float smf[];
    float* sx = smf;
    float* sy = smf + NN;
    float* sz = smf + 2 * NN;
    __shared__ float rv[32];
    __shared__ int   ri[32];
    __shared__ int   s_far;

    const float* base = xyz + (size_t)b * NN * 3;
    const int t = threadIdx.x;
    for (int i = t; i < NN; i += 1024) {
        float x = base[3 * i + 0];
        float y = base[3 * i + 1];
        float z = base[3 * i + 2];
        sx[i] = x; sy[i] = y; sz[i] = z;
    }
    float dist[16];
#pragma unroll
    for (int j = 0; j < 16; j++) dist[j] = 1e10f;
    __syncthreads();

    int far = 0;
    const int w = t >> 5, l = t & 31;
    for (int s = 0; s < SS; s++) {
        const float cx = sx[far], cy = sy[far], cz = sz[far];
        if (t == 0) {
            float* o = newxyz + ((size_t)b * SS + s) * 3;
            o[0] = cx; o[1] = cy; o[2] = cz;
        }
        float bv = -1.0f;
        int bi = 0;
#pragma unroll
        for (int j = 0; j < 16; j++) {
            const int n = t + j * 1024;
            float dx = __fsub_rn(sx[n], cx);
            float dy = __fsub_rn(sy[n], cy);
            float dz = __fsub_rn(sz[n], cz);
            float d = __fadd_rn(__fadd_rn(__fmul_rn(dx, dx), __fmul_rn(dy, dy)),
                                __fmul_rn(dz, dz));
            float nd = fminf(dist[j], d);
            dist[j] = nd;
            if (nd > bv) { bv = nd; bi = n; }
        }
#pragma unroll
        for (int o = 16; o > 0; o >>= 1) {
            float ov = __shfl_down_sync(0xffffffffu, bv, o);
            int   oi = __shfl_down_sync(0xffffffffu, bi, o);
            if (ov > bv || (ov == bv && oi < bi)) { bv = ov; bi = oi; }
        }
        if (l == 0) { rv[w] = bv; ri[w] = bi; }
        __syncthreads();
        if (w == 0) {
            bv = rv[l]; bi = ri[l];
#pragma unroll
            for (int o = 16; o > 0; o >>= 1) {
                float ov = __shfl_down_sync(0xffffffffu, bv, o);
                int   oi = __shfl_down_sync(0xffffffffu, bi, o);
                if (ov > bv || (ov == bv && oi < bi)) { bv = ov; bi = oi; }
            }
            if (l == 0) s_far = bi;
        }
        __syncthreads();
        far = s_far;
    }
}

// ---------------------------------------------------------------------------
// Stage 2: 32 nearest neighbors per centroid. One warp per centroid; the warp
// holds the current best-32 distributed one-per-lane; threshold = warp max via
// REDUX on float bits (all distances >= 0). Only the index SET matters.
// ---------------------------------------------------------------------------
__global__ __launch_bounds__(512, 1) void knn_kernel(const float* __restrict__ xyz,
                                                     const float* __restrict__ newxyz)
{
    const int blk = blockIdx.x;
    const int b = blk / (SS / 16);
    const int s0 = (blk % (SS / 16)) * 16;
    extern __shared__ float smf[];
    float* sx = smf;
    float* sy = smf + NN;
    float* sz = smf + 2 * NN;
    const float* base = xyz + (size_t)b * NN * 3;
    for (int i = threadIdx.x; i < NN; i += 512) {
        sx[i] = base[3 * i + 0];
        sy[i] = base[3 * i + 1];
        sz[i] = base[3 * i + 2];
    }
    __syncthreads();

    const int w = threadIdx.x >> 5, l = threadIdx.x & 31;
    const int srow = s0 + w;
    const float* q = newxyz + ((size_t)b * SS + srow) * 3;
    const float qx = q[0], qy = q[1], qz = q[2];

    float dx = sx[l] - qx, dy = sy[l] - qy, dz = sz[l] - qz;
    float val = fmaf(dx, dx, fmaf(dy, dy, dz * dz));
    int idx = l;
    unsigned tau = __reduce_max_sync(0xffffffffu, __float_as_uint(val));

    for (int n0 = 32; n0 < NN; n0 += 32) {
        const int n = n0 + l;
        float ax = sx[n] - qx, ay = sy[n] - qy, az = sz[n] - qz;
        float d = fmaf(ax, ax, fmaf(ay, ay, az * az));
        unsigned db = __float_as_uint(d);
        unsigned want = __ballot_sync(0xffffffffu, db < tau);
        while (want) {
            const int leader = __ffs(want) - 1;
            want &= (want - 1);
            unsigned cb = __shfl_sync(0xffffffffu, db, leader);
            if (cb < tau) {  // uniform across warp
                unsigned rm = __ballot_sync(0xffffffffu, __float_as_uint(val) == tau);
                const int r = __ffs(rm) - 1;
                if (l == r) { val = __uint_as_float(cb); idx = n0 + leader; }
                tau = __reduce_max_sync(0xffffffffu, __float_as_uint(val));
            }
        }
    }
    g_knn[((size_t)b * SS + srow) * KK + l] = idx;
}

// ---------------------------------------------------------------------------
// Stage 3: per-point pre-transform feat1 = features @ W1[3:67,:]  (gather is
// linear, so transform once per point instead of per (s,k) occurrence)
// ---------------------------------------------------------------------------
__global__ __launch_bounds__(256, 1) void pregemm_kernel(const float* __restrict__ feat,
                                                         const float* __restrict__ W1)
{
    __shared__ float sw[64 * 64];
    for (int i = threadIdx.x; i < 64 * 64; i += 256) sw[i] = W1[192 + i];
    __syncthreads();
    const int row = blockIdx.x * 256 + threadIdx.x;
    const float4* f4 = (const float4*)(feat + (size_t)row * 64);
    float acc[64];
#pragma unroll
    for (int j = 0; j < 64; j++) acc[j] = 0.f;
    for (int i4 = 0; i4 < 16; i4++) {
        float4 fv = f4[i4];
        const float4* w0 = (const float4*)(sw + (i4 * 4 + 0) * 64);
        const float4* w1 = (const float4*)(sw + (i4 * 4 + 1) * 64);
        const float4* w2 = (const float4*)(sw + (i4 * 4 + 2) * 64);
        const float4* w3 = (const float4*)(sw + (i4 * 4 + 3) * 64);
#pragma unroll
        for (int jv = 0; jv < 16; jv++) {
            float4 a0 = w0[jv], a1 = w1[jv], a2 = w2[jv], a3 = w3[jv];
            acc[jv * 4 + 0] = fmaf(fv.x, a0.x, fmaf(fv.y, a1.x, fmaf(fv.z, a2.x, fmaf(fv.w, a3.x, acc[jv * 4 + 0]))));
            acc[jv * 4 + 1] = fmaf(fv.x, a0.y, fmaf(fv.y, a1.y, fmaf(fv.z, a2.y, fmaf(fv.w, a3.y, acc[jv * 4 + 1]))));
            acc[jv * 4 + 2] = fmaf(fv.x, a0.z, fmaf(fv.y, a1.z, fmaf(fv.z, a2.z, fmaf(fv.w, a3.z, acc[jv * 4 + 2]))));
            acc[jv * 4 + 3] = fmaf(fv.x, a0.w, fmaf(fv.y, a1.w, fmaf(fv.z, a2.w, fmaf(fv.w, a3.w, acc[jv * 4 + 3]))));
        }
    }
    float4* o4 = (float4*)(g_feat1 + (size_t)row * 64);
#pragma unroll
    for (int jv = 0; jv < 16; jv++)
        o4[jv] = make_float4(acc[jv * 4], acc[jv * 4 + 1], acc[jv * 4 + 2], acc[jv * 4 + 3]);
}

// ---------------------------------------------------------------------------
// Stage 4: gather + MLP (67->64->64->128, relu) + max over K=32.
// Warp per centroid, lane per neighbor. Weights in SMEM (broadcast float4
// loads = 1 LDS per 4 FMA). Activations staged in per-warp SMEM so the
// reduction-dim loops stay un-unrolled with register accumulators.
// ---------------------------------------------------------------------------
__global__ __launch_bounds__(256, 1) void mlp_kernel(const float* __restrict__ xyz,
                                                     const float* __restrict__ newxyz,
                                                     const float* __restrict__ W1,
                                                     const float* __restrict__ b1,
                                                     const float* __restrict__ W2,
                                                     const float* __restrict__ b2,
                                                     const float* __restrict__ W3,
                                                     const float* __restrict__ b3,
                                                     float* __restrict__ outfeat)
{
    extern __shared__ float smf[];
    float* sW1 = smf;              // 3*64  (xyz rows of W1)
    float* sb1 = smf + 192;        // 64
    float* sW2 = smf + 256;        // 64*64
    float* sb2 = smf + 4352;       // 64
    float* sW3 = smf + 4416;       // 64*128
    float* sb3 = smf + 12608;      // 128
    float* hbuf = smf + 12736;     // 8 warps * 2048

    const int tid = threadIdx.x;
    for (int i = tid; i < 192; i += 256) sW1[i] = W1[i];
    for (int i = tid; i < 4096; i += 256) sW2[i] = W2[i];
    for (int i = tid; i < 8192; i += 256) sW3[i] = W3[i];
    if (tid < 64) { sb1[tid] = b1[tid]; sb2[tid] = b2[tid]; }
    if (tid < 128) sb3[tid] = b3[tid];
    __syncthreads();

    const int w = tid >> 5, l = tid & 31;
    const int c = blockIdx.x * 8 + w;   // global centroid id
    const int b = c / SS;
    float* hb = hbuf + w * 2048;

    const int nb = g_knn[(size_t)c * KK + l];
    const float* p = xyz + ((size_t)b * NN + nb) * 3;
    const float px = p[0], py = p[1], pz = p[2];
    const float* q = newxyz + (size_t)c * 3;
    const float dx = px - q[0], dy = py - q[1], dz = pz - q[2];
    const float4* fg = (const float4*)(g_feat1 + ((size_t)b * NN + nb) * 64);

    // layer 1: feat1(gathered) + xyz_norm @ W1[0:3] + b1, relu -> SMEM
#pragma unroll
    for (int jv = 0; jv < 16; jv++) {
        float4 f = fg[jv];
        float4 bb = ((const float4*)sb1)[jv];
        float4 u0 = ((const float4*)sW1)[jv];
        float4 u1 = ((const float4*)(sW1 + 64))[jv];
        float4 u2 = ((const float4*)(sW1 + 128))[jv];
        float v0 = fmaxf(fmaf(dz, u2.x, fmaf(dy, u1.x, fmaf(dx, u0.x, f.x + bb.x))), 0.f);
        float v1 = fmaxf(fmaf(dz, u2.y, fmaf(dy, u1.y, fmaf(dx, u0.y, f.y + bb.y))), 0.f);
        float v2 = fmaxf(fmaf(dz, u2.z, fmaf(dy, u1.z, fmaf(dx, u0.z, f.z + bb.z))), 0.f);
        float v3 = fmaxf(fmaf(dz, u2.w, fmaf(dy, u1.w, fmaf(dx, u0.w, f.w + bb.w))), 0.f);
        hb[(jv * 4 + 0) * 32 + l] = v0;
        hb[(jv * 4 + 1) * 32 + l] = v1;
        hb[(jv * 4 + 2) * 32 + l] = v2;
        hb[(jv * 4 + 3) * 32 + l] = v3;
    }
    __syncwarp();

    // layer 2
    float h2[64];
#pragma unroll
    for (int jv = 0; jv < 16; jv++) {
        float4 bb = ((const float4*)sb2)[jv];
        h2[jv * 4] = bb.x; h2[jv * 4 + 1] = bb.y; h2[jv * 4 + 2] = bb.z; h2[jv * 4 + 3] = bb.w;
    }
    for (int i = 0; i < 64; i++) {
        float hi = hb[i * 32 + l];
        const float4* wr = (const float4*)(sW2 + i * 64);
#pragma unroll
        for (int jv = 0; jv < 16; jv++) {
            float4 ww = wr[jv];
            h2[jv * 4]     = fmaf(hi, ww.x, h2[jv * 4]);
            h2[jv * 4 + 1] = fmaf(hi, ww.y, h2[jv * 4 + 1]);
            h2[jv * 4 + 2] = fmaf(hi, ww.z, h2[jv * 4 + 2]);
            h2[jv * 4 + 3] = fmaf(hi, ww.w, h2[jv * 4 + 3]);
        }
    }
    __syncwarp();
#pragma unroll
    for (int j = 0; j < 64; j++) hb[j * 32 + l] = fmaxf(h2[j], 0.f);
    __syncwarp();

    // layer 3 (two 64-col halves) + relu + max over lanes (neighbors)
    float* of = outfeat + (size_t)c * 128;
#pragma unroll 1
    for (int h = 0; h < 2; h++) {
        float a[64];
#pragma unroll
        for (int jv = 0; jv < 16; jv++) {
            float4 bb = ((const float4*)(sb3 + h * 64))[jv];
            a[jv * 4] = bb.x; a[jv * 4 + 1] = bb.y; a[jv * 4 + 2] = bb.z; a[jv * 4 + 3] = bb.w;
        }
        for (int i = 0; i < 64; i++) {
            float hi = hb[i * 32 + l];
            const float4* wr = (const float4*)(sW3 + i * 128 + h * 64);
#pragma unroll
            for (int jv = 0; jv < 16; jv++) {
                float4 ww = wr[jv];
                a[jv * 4]     = fmaf(hi, ww.x, a[jv * 4]);
                a[jv * 4 + 1] = fmaf(hi, ww.y, a[jv * 4 + 1]);
                a[jv * 4 + 2] = fmaf(hi, ww.z, a[jv * 4 + 2]);
                a[jv * 4 + 3] = fmaf(hi, ww.w, a[jv * 4 + 3]);
            }
        }
        float r0 = 0.f, r1 = 0.f;
#pragma unroll
        for (int jj = 0; jj < 64; jj++) {
            float v = a[jj] > 0.f ? a[jj] : 0.f;  // relu; guarantees non-negative bits
            unsigned m = __reduce_max_sync(0xffffffffu, __float_as_uint(v));
            if ((jj & 31) == l) {
                if (jj < 32) r0 = __uint_as_float(m);
                else         r1 = __uint_as_float(m);
            }
        }
        of[h * 64 + l] = r0;
        of[h * 64 + 32 + l] = r1;
    }
}

// ---------------------------------------------------------------------------
extern "C" void kernel_launch(void* const* d_in, const int* in_sizes, int n_in,
                              void* d_out, int out_size)
{
    (void)in_sizes; (void)n_in; (void)out_size;
    const float* xyz  = (const float*)d_in[0];
    const float* feat = (const float*)d_in[1];
    const float* W1   = (const float*)d_in[2];
    const float* b1   = (const float*)d_in[3];
    const float* W2   = (const float*)d_in[4];
    const float* b2   = (const float*)d_in[5];
    const float* W3   = (const float*)d_in[6];
    const float* b3   = (const float*)d_in[7];

    float* newxyz  = (float*)d_out;                       // [B,S,3]
    float* outfeat = newxyz + (size_t)BB * SS * 3;        // [B,S,128]

    cudaFuncSetAttribute(fps_kernel, cudaFuncAttributeMaxDynamicSharedMemorySize, 3 * NN * 4);
    cudaFuncSetAttribute(knn_kernel, cudaFuncAttributeMaxDynamicSharedMemorySize, 3 * NN * 4);
    cudaFuncSetAttribute(mlp_kernel, cudaFuncAttributeMaxDynamicSharedMemorySize, 116480);

    pregemm_kernel<<<BB * NN / 256, 256>>>(feat, W1);
    fps_kernel<<<BB, 1024, 3 * NN * 4>>>(xyz, newxyz);
    knn_kernel<<<BB * SS / 16, 512, 3 * NN * 4>>>(xyz, newxyz);
    mlp_kernel<<<BB * SS / 8, 256, 116480>>>(xyz, newxyz, W1, b1, W2, b2, W3, b3, outfeat);
}

// round 2
// speedup vs baseline: 1.5652x; 1.5652x over previous
#include <cuda_runtime.h>
#include <cstdint>
#include <cstddef>

#define BB 8
#define NN 16384
#define CC 64
#define SS 2048
#define KK 32

typedef unsigned long long ull;

// Scratch (device globals: no allocation allowed)
__device__ float g_feat1[(size_t)BB * NN * 64];   // features @ W1[3:67,:]
__device__ int   g_knn[(size_t)BB * SS * KK];     // top-32 neighbor indices

#define ADD2(r,a,b) asm("add.rn.f32x2 %0,%1,%2;" : "=l"(r) : "l"(a), "l"(b))
#define MUL2(r,a,b) asm("mul.rn.f32x2 %0,%1,%2;" : "=l"(r) : "l"(a), "l"(b))
#define PACK2(r,lo,hi) asm("mov.b64 %0,{%1,%2};" : "=l"(r) : "f"(lo), "f"(hi))
#define UNPACK2(lo,hi,v) asm("mov.b64 {%0,%1},%2;" : "=f"(lo), "=f"(hi) : "l"(v))

// ---------------------------------------------------------------------------
// Stage 1: farthest point sampling. One block per batch, 512 threads, 32 pts
// per thread. x,y in registers (packed pairs), z streamed from SMEM pairs.
// Packed f32x2 add/mul keep bit-identical rounding to the reference's
// sub/mul/add/add sequence. Argmax = FMNMX max-track + REDUX, then a gated
// equality pass that recovers the lowest index (first-index tie-break).
// ---------------------------------------------------------------------------
__global__ __launch_bounds__(512, 1) void fps_kernel(const float* __restrict__ xyz,
                                                     float* __restrict__ newxyz)
{
    const int b = blockIdx.x;
    extern __shared__ float smf[];
    float* sx = smf;
    float* sy = smf + NN;
    float* sz = smf + 2 * NN;
    __shared__ float rv[16];
    __shared__ int   ri[16];
    __shared__ float sM;
    __shared__ int   s_far;

    const float* base = xyz + (size_t)b * NN * 3;
    const int t = threadIdx.x;
    for (int i = t; i < NN; i += 512) {
        sx[i] = base[3 * i + 0];
        sy[i] = base[3 * i + 1];
        sz[i] = base[3 * i + 2];
    }
    __syncthreads();

    // thread t owns point-pairs p = t + 512k (points 2p, 2p+1)
    ull px[16], py[16];
    float dist[32];
#pragma unroll
    for (int k = 0; k < 16; k++) {
        const int p = t + 512 * k;
        px[k] = *(const ull*)(sx + 2 * p);
        py[k] = *(const ull*)(sy + 2 * p);
        dist[2 * k] = 1e10f; dist[2 * k + 1] = 1e10f;
    }

    const int w = t >> 5, l = t & 31;
    int far = 0;
    for (int s = 0; s < SS; s++) {
        const float cx = sx[far], cy = sy[far], cz = sz[far];
        if (t == 0) {
            float* o = newxyz + ((size_t)b * SS + s) * 3;
            o[0] = cx; o[1] = cy; o[2] = cz;
        }
        ull ncx, ncy, ncz;
        {
            float mx0 = -cx, my0 = -cy, mz0 = -cz;
            PACK2(ncx, mx0, mx0); PACK2(ncy, my0, my0); PACK2(ncz, mz0, mz0);
        }
        float mx = 0.f;
#pragma unroll
        for (int k = 0; k < 16; k++) {
            ull zp = *(const ull*)(sz + 2 * (t + 512 * k));
            ull dx, dy, dz, xx, yy, zz, s1, dd;
            ADD2(dx, px[k], ncx);
            ADD2(dy, py[k], ncy);
            ADD2(dz, zp, ncz);
            MUL2(xx, dx, dx);
            MUL2(yy, dy, dy);
            MUL2(zz, dz, dz);
            ADD2(s1, xx, yy);
            ADD2(dd, s1, zz);
            float d0, d1; UNPACK2(d0, d1, dd);
            float a0 = fminf(dist[2 * k], d0);     dist[2 * k] = a0;
            float a1 = fminf(dist[2 * k + 1], d1); dist[2 * k + 1] = a1;
            mx = fmaxf(mx, a0);
            mx = fmaxf(mx, a1);
        }
        // block max (all dists >= 0 -> uint bit compare valid)
        unsigned wv = __reduce_max_sync(0xffffffffu, __float_as_uint(mx));
        if (l == 0) rv[w] = __uint_as_float(wv);
        __syncthreads();
        if (w == 0) {
            float vv = (l < 16) ? rv[l] : 0.f;
            unsigned Mv = __reduce_max_sync(0xffffffffu, __float_as_uint(vv));
            if (l == 0) sM = __uint_as_float(Mv);
        }
        __syncthreads();
        const float M = sM;
        // index recovery: only threads holding the max scan their 32 values
        int n = 0x7fffffff;
        if (mx == M) {
            unsigned m = 0;
#pragma unroll
            for (int k = 0; k < 16; k++) {
                if (dist[2 * k] == M)     m |= 1u << (2 * k);
                if (dist[2 * k + 1] == M) m |= 1u << (2 * k + 1);
            }
            const int bb2 = __ffs(m) - 1;
            n = 2 * (t + 512 * (bb2 >> 1)) + (bb2 & 1);
        }
        n = __reduce_min_sync(0xffffffffu, n);
        if (l == 0) ri[w] = n;
        __syncthreads();
        if (w == 0) {
            int nn = (l < 16) ? ri[l] : 0x7fffffff;
            nn = __reduce_min_sync(0xffffffffu, nn);
            if (l == 0) s_far = nn;
        }
        __syncthreads();
        far = s_far;
    }
}

// ---------------------------------------------------------------------------
// Stage 2: 32 nearest neighbors per centroid via the reference's gemm
// identity d = (q2 + x2) - 2*cross. Points cached as float4 (x,y,z,x2) in
// two SMEM chunks. Distributed warp top-32 with sortable-uint keys (identity
// can go slightly negative for the self-point).
// ---------------------------------------------------------------------------
#define CHUNK 8192
__global__ __launch_bounds__(512, 1) void knn_kernel(const float* __restrict__ xyz,
                                                     const float* __restrict__ newxyz)
{
    const int blk = blockIdx.x;
    const int b = blk >> 7;              // / 128
    const int s0 = (blk & 127) * 16;
    extern __shared__ float4 sp[];       // 8192 float4 = 128KB
    const int tid = threadIdx.x, w = tid >> 5, l = tid & 31;
    const int srow = s0 + w;
    const float* q = newxyz + ((size_t)b * SS + srow) * 3;
    const float qx = q[0], qy = q[1], qz = q[2];
    const float q2 = __fadd_rn(__fadd_rn(__fmul_rn(qx, qx), __fmul_rn(qy, qy)),
                               __fmul_rn(qz, qz));
    unsigned val = 0, tau = 0;
    int idx = 0;
    const float* base = xyz + (size_t)b * NN * 3;

    for (int c = 0; c < 2; c++) {
        const int nb = c * CHUNK;
        for (int i = tid; i < CHUNK; i += 512) {
            const float x = base[3 * (nb + i) + 0];
            const float y = base[3 * (nb + i) + 1];
            const float z = base[3 * (nb + i) + 2];
            const float x2 = __fadd_rn(__fadd_rn(__fmul_rn(x, x), __fmul_rn(y, y)),
                                       __fmul_rn(z, z));
            sp[i] = make_float4(x, y, z, x2);
        }
        __syncthreads();

        int n0 = 0;
        if (c == 0) {
            float4 p = sp[l];
            float cross = __fmaf_rn(p.z, qz, __fmaf_rn(p.y, qy, __fmul_rn(p.x, qx)));
            float d = __fmaf_rn(-2.f, cross, __fadd_rn(q2, p.w));
            unsigned bb = __float_as_uint(d);
            val = bb ^ (unsigned)(((int)bb >> 31) | 0x80000000);
            idx = l;
            tau = __reduce_max_sync(0xffffffffu, val);
            n0 = 32;
        }
        for (; n0 < CHUNK; n0 += 32) {
            float4 p = sp[n0 + l];
            float cross = __fmaf_rn(p.z, qz, __fmaf_rn(p.y, qy, __fmul_rn(p.x, qx)));
            float d = __fmaf_rn(-2.f, cross, __fadd_rn(q2, p.w));
            unsigned bb = __float_as_uint(d);
            unsigned du = bb ^ (unsigned)(((int)bb >> 31) | 0x80000000);
            unsigned want = __ballot_sync(0xffffffffu, du < tau);
            while (want) {
                const int leader = __ffs(want) - 1;
                want &= (want - 1);
                unsigned cb = __shfl_sync(0xffffffffu, du, leader);
                if (cb < tau) {  // uniform
                    unsigned rm = __ballot_sync(0xffffffffu, val == tau);
                    const int r = __ffs(rm) - 1;
                    if (l == r) { val = cb; idx = nb + n0 + leader; }
                    tau = __reduce_max_sync(0xffffffffu, val);
                }
            }
        }
        __syncthreads();
    }
    g_knn[((size_t)b * SS + srow) * KK + l] = idx;
}

// ---------------------------------------------------------------------------
// Stage 3: per-point pre-transform feat1 = features @ W1[3:67,:]
// ---------------------------------------------------------------------------
__global__ __launch_bounds__(256, 1) void pregemm_kernel(const float* __restrict__ feat,
                                                         const float* __restrict__ W1)
{
    __shared__ float sw[64 * 64];
    for (int i = threadIdx.x; i < 64 * 64; i += 256) sw[i] = W1[192 + i];
    __syncthreads();
    const int row = blockIdx.x * 256 + threadIdx.x;
    const float4* f4 = (const float4*)(feat + (size_t)row * 64);
    float acc[64];
#pragma unroll
    for (int j = 0; j < 64; j++) acc[j] = 0.f;
    for (int i4 = 0; i4 < 16; i4++) {
        float4 fv = f4[i4];
        const float4* w0 = (const float4*)(sw + (i4 * 4 + 0) * 64);
        const float4* w1 = (const float4*)(sw + (i4 * 4 + 1) * 64);
        const float4* w2 = (const float4*)(sw + (i4 * 4 + 2) * 64);
        const float4* w3 = (const float4*)(sw + (i4 * 4 + 3) * 64);
#pragma unroll
        for (int jv = 0; jv < 16; jv++) {
            float4 a0 = w0[jv], a1 = w1[jv], a2 = w2[jv], a3 = w3[jv];
            acc[jv * 4 + 0] = fmaf(fv.x, a0.x, fmaf(fv.y, a1.x, fmaf(fv.z, a2.x, fmaf(fv.w, a3.x, acc[jv * 4 + 0]))));
            acc[jv * 4 + 1] = fmaf(fv.x, a0.y, fmaf(fv.y, a1.y, fmaf(fv.z, a2.y, fmaf(fv.w, a3.y, acc[jv * 4 + 1]))));
            acc[jv * 4 + 2] = fmaf(fv.x, a0.z, fmaf(fv.y, a1.z, fmaf(fv.z, a2.z, fmaf(fv.w, a3.z, acc[jv * 4 + 2]))));
            acc[jv * 4 + 3] = fmaf(fv.x, a0.w, fmaf(fv.y, a1.w, fmaf(fv.z, a2.w, fmaf(fv.w, a3.w, acc[jv * 4 + 3]))));
        }
    }
    float4* o4 = (float4*)(g_feat1 + (size_t)row * 64);
#pragma unroll
    for (int jv = 0; jv < 16; jv++)
        o4[jv] = make_float4(acc[jv * 4], acc[jv * 4 + 1], acc[jv * 4 + 2], acc[jv * 4 + 3]);
}

// ---------------------------------------------------------------------------
// Stage 4: gather + MLP + max over K. SMEM cut to 112KB/block (W1/biases via
// __ldg broadcast L1 hits) -> 2 blocks/SM, 16 warps/SM.
// ---------------------------------------------------------------------------
__global__ __launch_bounds__(256, 2) void mlp_kernel(const float* __restrict__ xyz,
                                                     const float* __restrict__ newxyz,
                                                     const float* __restrict__ W1,
                                                     const float* __restrict__ b1,
                                                     const float* __restrict__ W2,
                                                     const float* __restrict__ b2,
                                                     const float* __restrict__ W3,
                                                     const float* __restrict__ b3,
                                                     float* __restrict__ outfeat)
{
    extern __shared__ float smf[];
    float* sW2 = smf;              // 64*64
    float* sW3 = smf + 4096;       // 64*128
    float* hbuf = smf + 12288;     // 8 warps * 2048

    const int tid = threadIdx.x;
    for (int i = tid; i < 4096; i += 256) sW2[i] = W2[i];
    for (int i = tid; i < 8192; i += 256) sW3[i] = W3[i];
    __syncthreads();

    const int w = tid >> 5, l = tid & 31;
    const int c = blockIdx.x * 8 + w;   // global centroid id
    const int b = c / SS;
    float* hb = hbuf + w * 2048;

    const int nb = g_knn[(size_t)c * KK + l];
    const float* p = xyz + ((size_t)b * NN + nb) * 3;
    const float px = p[0], py = p[1], pz = p[2];
    const float* q = newxyz + (size_t)c * 3;
    const float dx = px - q[0], dy = py - q[1], dz = pz - q[2];
    const float4* fg = (const float4*)(g_feat1 + ((size_t)b * NN + nb) * 64);

    // layer 1: feat1(gathered) + xyz_norm @ W1[0:3] + b1, relu -> SMEM
#pragma unroll
    for (int jv = 0; jv < 16; jv++) {
        float4 f = fg[jv];
        float4 bb = __ldg((const float4*)b1 + jv);
        float4 u0 = __ldg((const float4*)(W1) + jv);
        float4 u1 = __ldg((const float4*)(W1 + 64) + jv);
        float4 u2 = __ldg((const float4*)(W1 + 128) + jv);
        float v0 = fmaxf(fmaf(dz, u2.x, fmaf(dy, u1.x, fmaf(dx, u0.x, f.x + bb.x))), 0.f);
        float v1 = fmaxf(fmaf(dz, u2.y, fmaf(dy, u1.y, fmaf(dx, u0.y, f.y + bb.y))), 0.f);
        float v2 = fmaxf(fmaf(dz, u2.z, fmaf(dy, u1.z, fmaf(dx, u0.z, f.z + bb.z))), 0.f);
        float v3 = fmaxf(fmaf(dz, u2.w, fmaf(dy, u1.w, fmaf(dx, u0.w, f.w + bb.w))), 0.f);
        hb[(jv * 4 + 0) * 32 + l] = v0;
        hb[(jv * 4 + 1) * 32 + l] = v1;
        hb[(jv * 4 + 2) * 32 + l] = v2;
        hb[(jv * 4 + 3) * 32 + l] = v3;
    }
    __syncwarp();

    // layer 2
    float h2[64];
#pragma unroll
    for (int jv = 0; jv < 16; jv++) {
        float4 bb = __ldg((const float4*)b2 + jv);
        h2[jv * 4] = bb.x; h2[jv * 4 + 1] = bb.y; h2[jv * 4 + 2] = bb.z; h2[jv * 4 + 3] = bb.w;
    }
    for (int i = 0; i < 64; i++) {
        float hi = hb[i * 32 + l];
        const float4* wr = (const float4*)(sW2 + i * 64);
#pragma unroll
        for (int jv = 0; jv < 16; jv++) {
            float4 ww = wr[jv];
            h2[jv * 4]     = fmaf(hi, ww.x, h2[jv * 4]);
            h2[jv * 4 + 1] = fmaf(hi, ww.y, h2[jv * 4 + 1]);
            h2[jv * 4 + 2] = fmaf(hi, ww.z, h2[jv * 4 + 2]);
            h2[jv * 4 + 3] = fmaf(hi, ww.w, h2[jv * 4 + 3]);
        }
    }
    __syncwarp();
#pragma unroll
    for (int j = 0; j < 64; j++) hb[j * 32 + l] = fmaxf(h2[j], 0.f);
    __syncwarp();

    // layer 3 (two 64-col halves) + relu + max over lanes (neighbors)
    float* of = outfeat + (size_t)c * 128;
#pragma unroll 1
    for (int h = 0; h < 2; h++) {
        float a[64];
#pragma unroll
        for (int jv = 0; jv < 16; jv++) {
            float4 bb = __ldg((const float4*)b3 + h * 16 + jv);
            a[jv * 4] = bb.x; a[jv * 4 + 1] = bb.y; a[jv * 4 + 2] = bb.z; a[jv * 4 + 3] = bb.w;
        }
        for (int i = 0; i < 64; i++) {
            float hi = hb[i * 32 + l];
            const float4* wr = (const float4*)(sW3 + i * 128 + h * 64);
#pragma unroll
            for (int jv = 0; jv < 16; jv++) {
                float4 ww = wr[jv];
                a[jv * 4]     = fmaf(hi, ww.x, a[jv * 4]);
                a[jv * 4 + 1] = fmaf(hi, ww.y, a[jv * 4 + 1]);
                a[jv * 4 + 2] = fmaf(hi, ww.z, a[jv * 4 + 2]);
                a[jv * 4 + 3] = fmaf(hi, ww.w, a[jv * 4 + 3]);
            }
        }
        float r0 = 0.f, r1 = 0.f;
#pragma unroll
        for (int jj = 0; jj < 64; jj++) {
            float v = a[jj] > 0.f ? a[jj] : 0.f;  // relu; non-negative bits
            unsigned m = __reduce_max_sync(0xffffffffu, __float_as_uint(v));
            if ((jj & 31) == l) {
                if (jj < 32) r0 = __uint_as_float(m);
                else         r1 = __uint_as_float(m);
            }
        }
        of[h * 64 + l] = r0;
        of[h * 64 + 32 + l] = r1;
    }
}

// ---------------------------------------------------------------------------
extern "C" void kernel_launch(void* const* d_in, const int* in_sizes, int n_in,
                              void* d_out, int out_size)
{
    (void)in_sizes; (void)n_in; (void)out_size;
    const float* xyz  = (const float*)d_in[0];
    const float* feat = (const float*)d_in[1];
    const float* W1   = (const float*)d_in[2];
    const float* b1   = (const float*)d_in[3];
    const float* W2   = (const float*)d_in[4];
    const float* b2   = (const float*)d_in[5];
    const float* W3   = (const float*)d_in[6];
    const float* b3   = (const float*)d_in[7];

    float* newxyz  = (float*)d_out;                       // [B,S,3]
    float* outfeat = newxyz + (size_t)BB * SS * 3;        // [B,S,128]

    cudaFuncSetAttribute(fps_kernel, cudaFuncAttributeMaxDynamicSharedMemorySize, 3 * NN * 4);
    cudaFuncSetAttribute(knn_kernel, cudaFuncAttributeMaxDynamicSharedMemorySize, CHUNK * 16);
    cudaFuncSetAttribute(mlp_kernel, cudaFuncAttributeMaxDynamicSharedMemorySize, 114688);

    pregemm_kernel<<<BB * NN / 256, 256>>>(feat, W1);
    fps_kernel<<<BB, 512, 3 * NN * 4>>>(xyz, newxyz);
    knn_kernel<<<BB * SS / 16, 512, CHUNK * 16>>>(xyz, newxyz);
    mlp_kernel<<<BB * SS / 8, 256, 114688>>>(xyz, newxyz, W1, b1, W2, b2, W3, b3, outfeat);
}

// round 4
// speedup vs baseline: 2.1148x; 1.3512x over previous
#include <cuda_runtime.h>
#include <cstdint>
#include <cstddef>

#define BB 8
#define NN 16384
#define CC 64
#define SS 2048
#define KK 32

typedef unsigned long long ull;

// Scratch (device globals: no allocation allowed)
__device__ float g_feat1[(size_t)BB * NN * 64];   // features @ W1[3:67,:]
__device__ int   g_knn[(size_t)BB * SS * KK];     // top-32 neighbor indices

#define ADD2(r,a,b) asm("add.rn.f32x2 %0,%1,%2;" : "=l"(r) : "l"(a), "l"(b))
#define MUL2(r,a,b) asm("mul.rn.f32x2 %0,%1,%2;" : "=l"(r) : "l"(a), "l"(b))
#define FMA2(r,a,b,c) asm("fma.rn.f32x2 %0,%1,%2,%3;" : "=l"(r) : "l"(a), "l"(b), "l"(c))
#define PACK2(r,lo,hi) asm("mov.b64 %0,{%1,%2};" : "=l"(r) : "f"(lo), "f"(hi))
#define UNPACK2(lo,hi,v) asm("mov.b64 {%0,%1},%2;" : "=f"(lo), "=f"(hi) : "l"(v))

__device__ __forceinline__ uint32_t smem_u32(const void* p) {
    uint32_t a;
    asm("{ .reg .u64 t; cvta.to.shared.u64 t, %1; cvt.u32.u64 %0, t; }" : "=r"(a) : "l"(p));
    return a;
}
__device__ __forceinline__ uint32_t cluster_rank() {
    uint32_t r; asm("mov.u32 %0, %%cluster_ctarank;" : "=r"(r)); return r;
}
__device__ __forceinline__ void st_cluster_u64(uint32_t laddr, uint32_t rnk, ull v) {
    asm volatile("{ .reg .b32 ra; mapa.shared::cluster.u32 ra, %0, %1; "
                 "st.shared::cluster.u64 [ra], %2; }"
                 :: "r"(laddr), "r"(rnk), "l"(v) : "memory");
}
#define MBARRIER_INIT(a, cnt) \
    asm volatile("mbarrier.init.shared.b64 [%0], %1;" :: "r"(a), "r"((uint32_t)(cnt)) : "memory")
#define MBARRIER_ARRIVE_CLUSTER(a, rnk) \
    asm volatile("{ .reg .b32 ra; mapa.shared::cluster.u32 ra, %0, %1; " \
                 "mbarrier.arrive.shared::cluster.b64 _, [ra]; }" \
                 :: "r"(a), "r"((uint32_t)(rnk)) : "memory")
#define MBARRIER_WAIT_PARITY(a, par) do {                                   \
    uint32_t _m = (a), _p = (uint32_t)(par), _d;                            \
    asm volatile("{ .reg .pred p; "                                         \
        "mbarrier.try_wait.parity.acquire.cta.shared::cta.b64 p, [%1], %2; " \
        "selp.b32 %0, 1, 0, p; }" : "=r"(_d) : "r"(_m), "r"(_p) : "memory"); \
    if (!_d) {                                                              \
        asm volatile("{ .reg .pred P1; WL_%=: "                             \
            "mbarrier.try_wait.parity.acquire.cta.shared::cta.b64 P1, [%0], %1, 0x989680; " \
            "@P1 bra.uni WD_%=; bra.uni WL_%=; WD_%=: }"                    \
            :: "r"(_m), "r"(_p) : "memory");                                \
    }                                                                       \
} while (0)
#define CLUSTER_SYNC() do { \
    asm volatile("barrier.cluster.arrive.aligned;" ::: "memory"); \
    asm volatile("barrier.cluster.wait.aligned;" ::: "memory"); } while (0)

// offset folded into the address register (nvcc rejects "n"(expr) pre-unroll)
#define LDSV2(w0, w1, addr) \
    asm("ld.shared.v2.u64 {%0,%1}, [%2];" : "=l"(w0), "=l"(w1) : "r"(addr))

// ---------------------------------------------------------------------------
// Stage 1: FPS, 8-CTA cluster per batch (64 SMs). Each CTA owns 2048 points
// (4/thread, packed pairs fully register-resident). Per iteration: local
// update + block argmax, then DSMEM mailbox push of {key, coords} to all 8
// ranks + remote mbarrier arrive; everyone waits on its LOCAL mbarrier and
// selects the winner uniformly. Distance arithmetic identical to R2 (packed
// add/mul sequence == reference's sub/mul/add/add). Mailboxes parity-double-
// buffered; release(arrive)/acquire(wait) pairs order data vs. flag per rank.
// ---------------------------------------------------------------------------
#define FPS_CTAS 8
#define FPS_PTS (NN / FPS_CTAS)   // 2048

__global__ __launch_bounds__(512, 1) __cluster_dims__(FPS_CTAS, 1, 1)
void fps_kernel(const float* __restrict__ xyz, float* __restrict__ newxyz)
{
    __shared__ alignas(16) float sx[FPS_PTS], sy[FPS_PTS], sz[FPS_PTS];
    __shared__ ull mbox[2][FPS_CTAS][3];
    __shared__ unsigned redv[16];
    __shared__ int redi[16];
    __shared__ alignas(8) ull mbar;

    const unsigned rank = cluster_rank();
    const int b = blockIdx.x / FPS_CTAS;
    const int t = threadIdx.x;
    const int w = t >> 5, l = t & 31;
    const int pbase = rank * FPS_PTS;
    const float* base = xyz + (size_t)b * NN * 3 + (size_t)pbase * 3;
    for (int i = t; i < FPS_PTS; i += 512) {
        sx[i] = base[3 * i + 0];
        sy[i] = base[3 * i + 1];
        sz[i] = base[3 * i + 2];
    }
    const uint32_t mbar_a = smem_u32(&mbar);
    if (t == 0) MBARRIER_INIT(mbar_a, FPS_CTAS);
    __syncthreads();
    CLUSTER_SYNC();   // all mbarriers + smem tiles ready cluster-wide

    // 2 packed pairs per thread, fully in registers
    ull px[2], py[2], pz[2];
    float dist[4];
#pragma unroll
    for (int k = 0; k < 2; k++) {
        const int p = t + 512 * k;
        px[k] = *(const ull*)(sx + 2 * p);
        py[k] = *(const ull*)(sy + 2 * p);
        pz[k] = *(const ull*)(sz + 2 * p);
        dist[2 * k] = 1e10f; dist[2 * k + 1] = 1e10f;
    }

    const float* p0 = xyz + (size_t)b * NN * 3;
    float cx = p0[0], cy = p0[1], cz = p0[2];
    float* outp = newxyz + (size_t)b * SS * 3;

    for (int s = 0; s < SS; s++) {
        if (rank == 0 && t == 0) {
            outp[3 * s + 0] = cx; outp[3 * s + 1] = cy; outp[3 * s + 2] = cz;
        }
        ull ncx, ncy, ncz;
        {
            float mx0 = -cx, my0 = -cy, mz0 = -cz;
            PACK2(ncx, mx0, mx0); PACK2(ncy, my0, my0); PACK2(ncz, mz0, mz0);
        }
        float bv = -1.0f; int bi = 0;
#pragma unroll
        for (int k = 0; k < 2; k++) {
            ull dx, dy, dz, xx, yy, zz, s1, dd;
            ADD2(dx, px[k], ncx);
            ADD2(dy, py[k], ncy);
            ADD2(dz, pz[k], ncz);
            MUL2(xx, dx, dx);
            MUL2(yy, dy, dy);
            MUL2(zz, dz, dz);
            ADD2(s1, xx, yy);
            ADD2(dd, s1, zz);
            float d0, d1; UNPACK2(d0, d1, dd);
            float a0 = fminf(dist[2 * k], d0);     dist[2 * k] = a0;
            float a1 = fminf(dist[2 * k + 1], d1); dist[2 * k + 1] = a1;
            const int pl = 2 * (t + 512 * k);
            if (a0 > bv) { bv = a0; bi = pl; }
            if (a1 > bv) { bv = a1; bi = pl + 1; }
        }
        bi += pbase;                               // global index
        const unsigned vb = __float_as_uint(bv);   // dist >= 0 -> bit-order ok
        unsigned wv = __reduce_max_sync(0xffffffffu, vb);
        int cand = (vb == wv) ? bi : 0x7fffffff;
        int wi = __reduce_min_sync(0xffffffffu, cand);
        if (l == 0) { redv[w] = wv; redi[w] = wi; }
        __syncthreads();
        const int par = s & 1;
        if (w == 0) {
            unsigned v2 = (l < 16) ? redv[l] : 0u;
            int i2 = (l < 16) ? redi[l] : 0x7fffffff;
            unsigned bm = __reduce_max_sync(0xffffffffu, v2);
            int c2 = (v2 == bm) ? i2 : 0x7fffffff;
            int gi = __reduce_min_sync(0xffffffffu, c2);
            if (l < FPS_CTAS) {
                const int li = gi - pbase;         // this CTA's best is local
                const float wx = sx[li], wy = sy[li], wz = sz[li];
                const ull e0 = ((ull)bm << 32) | (unsigned)(~gi);
                const ull e1 = ((ull)__float_as_uint(wy) << 32) | __float_as_uint(wx);
                const ull e2 = (ull)__float_as_uint(wz);
                const uint32_t ma = smem_u32(&mbox[par][rank][0]);
                st_cluster_u64(ma, l, e0);
                st_cluster_u64(ma + 8, l, e1);
                st_cluster_u64(ma + 16, l, e2);
                MBARRIER_ARRIVE_CLUSTER(mbar_a, l);   // release: orders stores
            }
        }
        MBARRIER_WAIT_PARITY(mbar_a, par);            // acquire
        ull best = mbox[par][0][0]; int br = 0;
#pragma unroll
        for (int r = 1; r < FPS_CTAS; r++) {
            ull e = mbox[par][r][0];
            if (e > best) { best = e; br = r; }
        }
        const ull e1 = mbox[par][br][1];
        const ull e2 = mbox[par][br][2];
        cx = __uint_as_float((unsigned)e1);
        cy = __uint_as_float((unsigned)(e1 >> 32));
        cz = __uint_as_float((unsigned)e2);
    }
}

// ---------------------------------------------------------------------------
// Stage 2: 32 nearest neighbors per centroid (unchanged from R2).
// ---------------------------------------------------------------------------
#define CHUNK 8192
__global__ __launch_bounds__(512, 1) void knn_kernel(const float* __restrict__ xyz,
                                                     const float* __restrict__ newxyz)
{
    const int blk = blockIdx.x;
    const int b = blk >> 7;
    const int s0 = (blk & 127) * 16;
    extern __shared__ float4 sp[];
    const int tid = threadIdx.x, w = tid >> 5, l = tid & 31;
    const int srow = s0 + w;
    const float* q = newxyz + ((size_t)b * SS + srow) * 3;
    const float qx = q[0], qy = q[1], qz = q[2];
    const float q2 = __fadd_rn(__fadd_rn(__fmul_rn(qx, qx), __fmul_rn(qy, qy)),
                               __fmul_rn(qz, qz));
    unsigned val = 0, tau = 0;
    int idx = 0;
    const float* base = xyz + (size_t)b * NN * 3;

    for (int c = 0; c < 2; c++) {
        const int nb = c * CHUNK;
        for (int i = tid; i < CHUNK; i += 512) {
            const float x = base[3 * (nb + i) + 0];
            const float y = base[3 * (nb + i) + 1];
            const float z = base[3 * (nb + i) + 2];
            const float x2 = __fadd_rn(__fadd_rn(__fmul_rn(x, x), __fmul_rn(y, y)),
                                       __fmul_rn(z, z));
            sp[i] = make_float4(x, y, z, x2);
        }
        __syncthreads();

        int n0 = 0;
        if (c == 0) {
            float4 p = sp[l];
            float cross = __fmaf_rn(p.z, qz, __fmaf_rn(p.y, qy, __fmul_rn(p.x, qx)));
            float d = __fmaf_rn(-2.f, cross, __fadd_rn(q2, p.w));
            unsigned bb = __float_as_uint(d);
            val = bb ^ (unsigned)(((int)bb >> 31) | 0x80000000);
            idx = l;
            tau = __reduce_max_sync(0xffffffffu, val);
            n0 = 32;
        }
        for (; n0 < CHUNK; n0 += 32) {
            float4 p = sp[n0 + l];
            float cross = __fmaf_rn(p.z, qz, __fmaf_rn(p.y, qy, __fmul_rn(p.x, qx)));
            float d = __fmaf_rn(-2.f, cross, __fadd_rn(q2, p.w));
            unsigned bb = __float_as_uint(d);
            unsigned du = bb ^ (unsigned)(((int)bb >> 31) | 0x80000000);
            unsigned want = __ballot_sync(0xffffffffu, du < tau);
            while (want) {
                const int leader = __ffs(want) - 1;
                want &= (want - 1);
                unsigned cb = __shfl_sync(0xffffffffu, du, leader);
                if (cb < tau) {
                    unsigned rm = __ballot_sync(0xffffffffu, val == tau);
                    const int r = __ffs(rm) - 1;
                    if (l == r) { val = cb; idx = nb + n0 + leader; }
                    tau = __reduce_max_sync(0xffffffffu, val);
                }
            }
        }
        __syncthreads();
    }
    g_knn[((size_t)b * SS + srow) * KK + l] = idx;
}

// ---------------------------------------------------------------------------
// Stage 3: per-point pre-transform feat1 = features @ W1[3:67,:] (unchanged)
// ---------------------------------------------------------------------------
__global__ __launch_bounds__(256, 1) void pregemm_kernel(const float* __restrict__ feat,
                                                         const float* __restrict__ W1)
{
    __shared__ float sw[64 * 64];
    for (int i = threadIdx.x; i < 64 * 64; i += 256) sw[i] = W1[192 + i];
    __syncthreads();
    const int row = blockIdx.x * 256 + threadIdx.x;
    const float4* f4 = (const float4*)(feat + (size_t)row * 64);
    float acc[64];
#pragma unroll
    for (int j = 0; j < 64; j++) acc[j] = 0.f;
    for (int i4 = 0; i4 < 16; i4++) {
        float4 fv = f4[i4];
        const float4* w0 = (const float4*)(sw + (i4 * 4 + 0) * 64);
        const float4* w1 = (const float4*)(sw + (i4 * 4 + 1) * 64);
        const float4* w2 = (const float4*)(sw + (i4 * 4 + 2) * 64);
        const float4* w3 = (const float4*)(sw + (i4 * 4 + 3) * 64);
#pragma unroll
        for (int jv = 0; jv < 16; jv++) {
            float4 a0 = w0[jv], a1 = w1[jv], a2 = w2[jv], a3 = w3[jv];
            acc[jv * 4 + 0] = fmaf(fv.x, a0.x, fmaf(fv.y, a1.x, fmaf(fv.z, a2.x, fmaf(fv.w, a3.x, acc[jv * 4 + 0]))));
            acc[jv * 4 + 1] = fmaf(fv.x, a0.y, fmaf(fv.y, a1.y, fmaf(fv.z, a2.y, fmaf(fv.w, a3.y, acc[jv * 4 + 1]))));
            acc[jv * 4 + 2] = fmaf(fv.x, a0.z, fmaf(fv.y, a1.z, fmaf(fv.z, a2.z, fmaf(fv.w, a3.z, acc[jv * 4 + 2]))));
            acc[jv * 4 + 3] = fmaf(fv.x, a0.w, fmaf(fv.y, a1.w, fmaf(fv.z, a2.w, fmaf(fv.w, a3.w, acc[jv * 4 + 3]))));
        }
    }
    float4* o4 = (float4*)(g_feat1 + (size_t)row * 64);
#pragma unroll
    for (int jv = 0; jv < 16; jv++)
        o4[jv] = make_float4(acc[jv * 4], acc[jv * 4 + 1], acc[jv * 4 + 2], acc[jv * 4 + 3]);
}

// ---------------------------------------------------------------------------
// Stage 4: gather + MLP + max over K. f32x2 packed accumulators (fma.rn.f32x2,
// per-element IEEE-identical), explicit ld.shared.v2.u64 weight broadcasts.
// hb is strictly lane-private -> no intra-warp syncs needed.
// ---------------------------------------------------------------------------
__global__ __launch_bounds__(256, 2) void mlp_kernel(const float* __restrict__ xyz,
                                                     const float* __restrict__ newxyz,
                                                     const float* __restrict__ W1,
                                                     const float* __restrict__ b1,
                                                     const float* __restrict__ W2,
                                                     const float* __restrict__ b2,
                                                     const float* __restrict__ W3,
                                                     const float* __restrict__ b3,
                                                     float* __restrict__ outfeat)
{
    extern __shared__ float smf[];
    float* sW2 = smf;              // 64*64
    float* sW3 = smf + 4096;       // 64*128
    float* hbuf = smf + 12288;     // 8 warps * 2048

    const int tid = threadIdx.x;
    for (int i = tid; i < 4096; i += 256) sW2[i] = W2[i];
    for (int i = tid; i < 8192; i += 256) sW3[i] = W3[i];
    __syncthreads();

    const int w = tid >> 5, l = tid & 31;
    const int c = blockIdx.x * 8 + w;
    const int b = c / SS;
    float* hb = hbuf + w * 2048;
    const uint32_t w2a = smem_u32(sW2);
    const uint32_t w3a = smem_u32(sW3);

    const int nb = g_knn[(size_t)c * KK + l];
    const float* p = xyz + ((size_t)b * NN + nb) * 3;
    const float px = p[0], py = p[1], pz = p[2];
    const float* q = newxyz + (size_t)c * 3;
    const float dx = px - q[0], dy = py - q[1], dz = pz - q[2];
    const float4* fg = (const float4*)(g_feat1 + ((size_t)b * NN + nb) * 64);

    // layer 1: feat1(gathered) + xyz_norm @ W1[0:3] + b1, relu -> hb
#pragma unroll
    for (int jv = 0; jv < 16; jv++) {
        float4 f = fg[jv];
        float4 bb = __ldg((const float4*)b1 + jv);
        float4 u0 = __ldg((const float4*)(W1) + jv);
        float4 u1 = __ldg((const float4*)(W1 + 64) + jv);
        float4 u2 = __ldg((const float4*)(W1 + 128) + jv);
        hb[(jv * 4 + 0) * 32 + l] = fmaxf(fmaf(dz, u2.x, fmaf(dy, u1.x, fmaf(dx, u0.x, f.x + bb.x))), 0.f);
        hb[(jv * 4 + 1) * 32 + l] = fmaxf(fmaf(dz, u2.y, fmaf(dy, u1.y, fmaf(dx, u0.y, f.y + bb.y))), 0.f);
        hb[(jv * 4 + 2) * 32 + l] = fmaxf(fmaf(dz, u2.z, fmaf(dy, u1.z, fmaf(dx, u0.z, f.z + bb.z))), 0.f);
        hb[(jv * 4 + 3) * 32 + l] = fmaxf(fmaf(dz, u2.w, fmaf(dy, u1.w, fmaf(dx, u0.w, f.w + bb.w))), 0.f);
    }

    // layer 2: packed pair accumulators
    ull acc[32];
    const ull* b2u = (const ull*)b2;
#pragma unroll
    for (int j = 0; j < 32; j++) acc[j] = __ldg(b2u + j);
    for (int i = 0; i < 64; i++) {
        const float hi = hb[i * 32 + l];
        ull hx; PACK2(hx, hi, hi);
        const uint32_t wr = w2a + i * 256;
#pragma unroll
        for (int j4 = 0; j4 < 16; j4++) {
            ull w0, w1;
            LDSV2(w0, w1, wr + j4 * 16);
            FMA2(acc[2 * j4],     hx, w0, acc[2 * j4]);
            FMA2(acc[2 * j4 + 1], hx, w1, acc[2 * j4 + 1]);
        }
    }
#pragma unroll
    for (int j = 0; j < 32; j++) {
        float lo, hi2; UNPACK2(lo, hi2, acc[j]);
        hb[(2 * j) * 32 + l]     = fmaxf(lo, 0.f);
        hb[(2 * j + 1) * 32 + l] = fmaxf(hi2, 0.f);
    }

    // layer 3 (two 64-col halves, packed) + relu + max over lanes
    float* of = outfeat + (size_t)c * 128;
    const ull* b3u = (const ull*)b3;
#pragma unroll 1
    for (int h = 0; h < 2; h++) {
        ull a[32];
#pragma unroll
        for (int j = 0; j < 32; j++) a[j] = __ldg(b3u + h * 32 + j);
        for (int i = 0; i < 64; i++) {
            const float hi = hb[i * 32 + l];
            ull hx; PACK2(hx, hi, hi);
            const uint32_t wr = w3a + i * 512 + h * 256;
#pragma unroll
            for (int j4 = 0; j4 < 16; j4++) {
                ull w0, w1;
                LDSV2(w0, w1, wr + j4 * 16);
                FMA2(a[2 * j4],     hx, w0, a[2 * j4]);
                FMA2(a[2 * j4 + 1], hx, w1, a[2 * j4 + 1]);
            }
        }
        float av[64];
#pragma unroll
        for (int j = 0; j < 32; j++) {
            float lo, hi2; UNPACK2(lo, hi2, a[j]);
            av[2 * j]     = lo > 0.f ? lo : 0.f;
            av[2 * j + 1] = hi2 > 0.f ? hi2 : 0.f;
        }
        float r0 = 0.f, r1 = 0.f;
#pragma unroll
        for (int jj = 0; jj < 64; jj++) {
            unsigned m = __reduce_max_sync(0xffffffffu, __float_as_uint(av[jj]));
            if ((jj & 31) == l) {
                if (jj < 32) r0 = __uint_as_float(m);
                else         r1 = __uint_as_float(m);
            }
        }
        of[h * 64 + l] = r0;
        of[h * 64 + 32 + l] = r1;
    }
}

// ---------------------------------------------------------------------------
extern "C" void kernel_launch(void* const* d_in, const int* in_sizes, int n_in,
                              void* d_out, int out_size)
{
    (void)in_sizes; (void)n_in; (void)out_size;
    const float* xyz  = (const float*)d_in[0];
    const float* feat = (const float*)d_in[1];
    const float* W1   = (const float*)d_in[2];
    const float* b1   = (const float*)d_in[3];
    const float* W2   = (const float*)d_in[4];
    const float* b2   = (const float*)d_in[5];
    const float* W3   = (const float*)d_in[6];
    const float* b3   = (const float*)d_in[7];

    float* newxyz  = (float*)d_out;                       // [B,S,3]
    float* outfeat = newxyz + (size_t)BB * SS * 3;        // [B,S,128]

    cudaFuncSetAttribute(knn_kernel, cudaFuncAttributeMaxDynamicSharedMemorySize, CHUNK * 16);
    cudaFuncSetAttribute(mlp_kernel, cudaFuncAttributeMaxDynamicSharedMemorySize, 114688);

    pregemm_kernel<<<BB * NN / 256, 256>>>(feat, W1);
    fps_kernel<<<BB * FPS_CTAS, 512>>>(xyz, newxyz);
    knn_kernel<<<BB * SS / 16, 512, CHUNK * 16>>>(xyz, newxyz);
    mlp_kernel<<<BB * SS / 8, 256, 114688>>>(xyz, newxyz, W1, b1, W2, b2, W3, b3, outfeat);
}